// round 16
// baseline (speedup 1.0000x reference)
#include <cuda_runtime.h>

// ---------------------------------------------------------------------------
// PatchTokenizer: hierarchical mask selection + compacted patch gathers.
//   mask_kernel (32 blocks): barrier-free redundant counting (R15, proven).
//   mega_kernel (15360 blocks): S0 unchanged; S3' fuses fulls0+resized1 (one
//     patch/block, region staged in smem -> resized1 needs NO extra DRAM
//     reads); S4' fuses fulls1+resized2 (half patch/block, 24KB smem).
// ---------------------------------------------------------------------------

#define OFF1 25165824
#define OFF2 31457280
#define OFF3 33030144
#define OFF4 58195968
#define OFF5 83361792
#define OFF6 83394560
#define OFF7 83402752
#define OFF8 83404800
#define OFF9 83404803
#define OFF10 83447843
#define OFF11 83447875
#define OFF12 83447908
#define OFF13 83447909

// scratch (allocation-free rule: __device__ globals; rewritten every launch)
__device__ int g_sel0[32768], g_sel1[8192], g_sel2[2048];
__device__ int g_cnt[3];

__device__ __forceinline__ float4 zero4() { return make_float4(0.f, 0.f, 0.f, 0.f); }

// ---- Mask kernel: 32 blocks x 256 threads, no cross-block sync (R15) -----
__global__ void __launch_bounds__(256)
mask_kernel(const float* __restrict__ imp1, const float* __restrict__ imp2,
            float* __restrict__ out) {
    const int b = blockIdx.x, tid = threadIdx.x;
    __shared__ unsigned char sm2all[2048];
    __shared__ unsigned char sm1[256];
    __shared__ int sC1[32], sC2[32];
    __shared__ unsigned short ssel0[1024], ssel1[256], ssel2[64];
    __shared__ int w0[8], w1[8], w2[8];
    __shared__ int sOff0, sOff1, sOff2, sStart, sTotAll;

#pragma unroll
    for (int k = 0; k < 8; k++) {
        int i = tid + k * 256;
        sm2all[i] = imp2[i] < 0.3f;
    }
    __syncthreads();

    {
        const int w = tid >> 5, l = tid & 31;
#pragma unroll
        for (int q = 0; q < 4; q++) {
            int bb = w * 4 + q;
            int c2p = (int)sm2all[bb * 64 + l] + (int)sm2all[bb * 64 + 32 + l];
            int c1p = 0;
#pragma unroll
            for (int k = 0; k < 8; k++) {
                int j = k * 32 + l;
                int r = j >> 4, c = j & 15;
                unsigned char cov2 = sm2all[bb * 64 + ((r >> 1) << 3) + (c >> 1)];
                c1p += (imp1[bb * 256 + j] < 0.5f) && !cov2;
            }
#pragma unroll
            for (int o = 16; o; o >>= 1) {
                c2p += __shfl_down_sync(0xffffffffu, c2p, o);
                c1p += __shfl_down_sync(0xffffffffu, c1p, o);
            }
            if (l == 0) { sC1[bb] = c1p; sC2[bb] = c2p; }
        }
    }
    __syncthreads();

    if (tid < 32) {
        int c1 = sC1[tid], c2 = sC2[tid];
        int c0 = 1024 - 16 * c2 - 4 * c1;
        int sl = 1 + c0 + c1 + c2;
        int x0 = c0, x1 = c1, x2 = c2, xs = sl;
#pragma unroll
        for (int o = 1; o < 32; o <<= 1) {
            int n0 = __shfl_up_sync(0xffffffffu, x0, o);
            int n1 = __shfl_up_sync(0xffffffffu, x1, o);
            int n2 = __shfl_up_sync(0xffffffffu, x2, o);
            int ns = __shfl_up_sync(0xffffffffu, xs, o);
            if (tid >= o) { x0 += n0; x1 += n1; x2 += n2; xs += ns; }
        }
        if (tid == b) {
            sOff0 = x0 - c0; sOff1 = x1 - c1; sOff2 = x2 - c2;
            sStart = xs - sl;
        }
        if (tid == 31) sTotAll = xs;
        if (b == 0) {
            out[OFF10 + tid] = (float)sl;
            out[OFF11 + 1 + tid] = (float)xs;
            int mx = sl;
#pragma unroll
            for (int o = 16; o; o >>= 1) {
                int n = __shfl_xor_sync(0xffffffffu, mx, o);
                mx = mx > n ? mx : n;
            }
            if (tid == 0) {
                out[OFF11] = 0.0f;
                out[OFF12] = (float)mx;
            }
            if (tid == 31) {
                g_cnt[0] = x0; g_cnt[1] = x1; g_cnt[2] = x2;
                out[OFF8 + 0] = (float)x0;
                out[OFF8 + 1] = (float)x1;
                out[OFF8 + 2] = (float)x2;
                out[OFF13] = (float)xs / 32768.0f;
            }
        }
    }
    __syncthreads();

    unsigned char v2 = 0;
    if (tid < 64) {
        v2 = sm2all[b * 64 + tid];
        out[OFF7 + b * 64 + tid] = (float)v2;
    }
    unsigned char v1;
    {
        int r = tid >> 4, c = tid & 15;
        unsigned char cov2 = sm2all[b * 64 + ((r >> 1) << 3) + (c >> 1)];
        v1 = (imp1[b * 256 + tid] < 0.5f) && !cov2;
        sm1[tid] = v1;
        out[OFF6 + b * 256 + tid] = (float)v1;
    }
    __syncthreads();

    unsigned char v0[4];
#pragma unroll
    for (int k = 0; k < 4; k++) {
        int j = tid * 4 + k;
        int r = j >> 5, c = j & 31;
        unsigned char cov = sm2all[b * 64 + ((r >> 2) << 3) + (c >> 2)] |
                            sm1[((r >> 1) << 4) + (c >> 1)];
        v0[k] = !cov;
        out[OFF5 + b * 1024 + j] = (float)v0[k];
    }

    const int lane = tid & 31, wid = tid >> 5;
    int s0 = v0[0] + v0[1] + v0[2] + v0[3];
    int a1 = (int)v1, a2 = (tid < 64) ? (int)v2 : 0;
    int i0 = s0, i1 = a1, i2 = a2;
#pragma unroll
    for (int o = 1; o < 32; o <<= 1) {
        int n0 = __shfl_up_sync(0xffffffffu, i0, o);
        int n1 = __shfl_up_sync(0xffffffffu, i1, o);
        int n2 = __shfl_up_sync(0xffffffffu, i2, o);
        if (lane >= o) { i0 += n0; i1 += n1; i2 += n2; }
    }
    if (lane == 31) { w0[wid] = i0; w1[wid] = i1; w2[wid] = i2; }
    __syncthreads();
    int base0 = 0, base1 = 0, base2 = 0, tot0 = 0, tot1 = 0, tot2 = 0;
#pragma unroll
    for (int k = 0; k < 8; k++) {
        if (k < wid) { base0 += w0[k]; base1 += w1[k]; base2 += w2[k]; }
        tot0 += w0[k]; tot1 += w1[k]; tot2 += w2[k];
    }
    {
        int r = base0 + i0 - s0;
#pragma unroll
        for (int k = 0; k < 4; k++)
            if (v0[k]) ssel0[r++] = (unsigned short)(tid * 4 + k);
    }
    if (v1) ssel1[base1 + i1 - a1] = (unsigned short)tid;
    if (tid < 64 && v2) ssel2[base2 + i2 - a2] = (unsigned short)tid;
    __syncthreads();

    for (int r = tid; r < tot0; r += 256)
        g_sel0[sOff0 + r] = (int)ssel0[r] + (b << 10);
    for (int r = tid; r < tot1; r += 256)
        g_sel1[sOff1 + r] = (int)ssel1[r] + (b << 8);
    for (int r = tid; r < tot2; r += 256)
        g_sel2[sOff2 + r] = (int)ssel2[r] + (b << 6);

    {
        const int seg = 1 + tot0 + tot1 + tot2;
        const int t01 = 1 + tot0;
        const int t012 = 1 + tot0 + tot1;
        for (int i = tid; i < seg; i += 256) {
            float v;
            if (i == 0) v = -1.0f;
            else if (i < t01) v = 1.0f;
            else if (i < t012) v = 2.0f;
            else v = 3.0f;
            out[OFF9 + sStart + i] = v;
        }
        const int tot = sTotAll;
        const int tail = 43040 - tot;
        const int chunk = (tail + 31) >> 5;
        const int lo = tot + b * chunk;
        int hi = lo + chunk;
        if (hi > 43040) hi = 43040;
        for (int j = lo + tid; j < hi; j += 256) out[OFF9 + j] = 0.0f;
    }
}

// ---------------------------------------------------------------------------
// Mega kernel: S0 | S3'(fulls0+resized1) | S4'(fulls1+resized2)
// ---------------------------------------------------------------------------
#define NB_A 3072     // S0 blocks
#define NB_B 8192     // S3' blocks (one fulls0 patch each)
#define NB_C 4096     // S4' blocks (half a fulls1 patch each)
#define EA (NB_A)
#define EB (NB_A + NB_B)
#define NBLK (NB_A + NB_B + NB_C)   // 15360

__global__ void __launch_bounds__(256)
mega_kernel(const float* __restrict__ img, float* __restrict__ out) {
    const int bs = blockIdx.x;
    const int tid = threadIdx.x;
    __shared__ float4 sm[1536];   // 24 KB: S3' uses 768, S4' uses 1536

    if (bs < EA) {
        // ---- S0: resized0 (pure copy of 16x16 base patches) --------------
        const int cnt = g_cnt[0];
        const int base = bs * 2048 + tid;
        int off[8];
#pragma unroll
        for (int k = 0; k < 8; k++) {
            int i = base + k * 256;
            int p = i / 192, t4 = i - p * 192;
            if (p < cnt) {
                int s = g_sel0[p];
                int b = s >> 10, gy = (s >> 5) & 31, gx = s & 31;
                int e = t4 << 2;
                int c = e >> 8, y = (e >> 4) & 15, x = e & 15;
                off[k] = ((b * 3 + c) * 512 + gy * 16 + y) * 512 + gx * 16 + x;
            } else off[k] = -1;
        }
        float4 v[8];
#pragma unroll
        for (int k = 0; k < 8; k++)
            v[k] = (off[k] >= 0) ? *reinterpret_cast<const float4*>(img + off[k]) : zero4();
        float4* dst = reinterpret_cast<float4*>(out);
#pragma unroll
        for (int k = 0; k < 8; k++) dst[base + k * 256] = v[k];

    } else if (bs < EB) {
        // ---- S3': one fulls0 patch + its resized1 row --------------------
        const int p = bs - EA;
        const bool sel = p < g_cnt[1];
        int b = 0, gy = 0, gx = 0;
        if (sel) {
            int s = g_sel1[p];
            b = s >> 8; gy = (s >> 4) & 15; gx = s & 15;
        }
        // load region 32x32x3: i=(c,y,x4), c=i>>8, y=(i>>3)&31, x4=i&7
        float4 v[3];
#pragma unroll
        for (int k = 0; k < 3; k++) {
            int i = tid + k * 256;
            if (sel) {
                int c = i >> 8, rem = i & 255, y = rem >> 3, x4 = rem & 7;
                v[k] = *reinterpret_cast<const float4*>(
                    img + ((b * 3 + c) * 512 + gy * 32 + y) * 512 + gx * 32 + x4 * 4);
            } else v[k] = zero4();
            sm[i] = v[k];
        }
        // fulls0 row p (768 f4) directly from registers, remapped
        {
            float4* d3 = reinterpret_cast<float4*>(out + OFF3) + (size_t)p * 768;
#pragma unroll
            for (int k = 0; k < 3; k++) {
                int i = tid + k * 256;
                int c = i >> 8, rem = i & 255, y = rem >> 3, x4 = rem & 7;
                int ny = y >> 4, nx = x4 >> 2;
                int j = (ny * 2 + nx) * 192 + c * 64 + (y & 15) * 4 + (x4 & 3);
                d3[j] = v[k];
            }
        }
        __syncthreads();
        // resized1 row p (192 f4) from smem
        if (tid < 192) {
            float4 o = zero4();
            if (sel) {
                int c = tid >> 6, y = (tid >> 2) & 15, xh = (tid & 3) * 2;  // xh = x/2
                int base1 = c * 256 + (2 * y) * 8 + xh;
                float4 a0 = sm[base1], a1 = sm[base1 + 1];
                float4 b0 = sm[base1 + 8], b1 = sm[base1 + 9];
                o.x = (a0.x + a0.y + b0.x + b0.y) * 0.25f;
                o.y = (a0.z + a0.w + b0.z + b0.w) * 0.25f;
                o.z = (a1.x + a1.y + b1.x + b1.y) * 0.25f;
                o.w = (a1.z + a1.w + b1.z + b1.w) * 0.25f;
            }
            reinterpret_cast<float4*>(out + OFF1)[(size_t)p * 192 + tid] = o;
        }

    } else {
        // ---- S4': half a fulls1 patch + half its resized2 row ------------
        const int idx = bs - EB;
        const int p2 = idx >> 1, half = idx & 1;
        const bool sel = p2 < g_cnt[2];
        int b = 0, gy = 0, gx = 0;
        if (sel) {
            int s = g_sel2[p2];
            b = s >> 6; gy = (s >> 3) & 7; gx = s & 7;
        }
        // load region rows [half*32, half*32+32) x 64 cols x 3 ch:
        // i=(c,y,x4): c=i>>9, y=(i>>4)&31, x4=i&15   (1536 f4)
        float4 v[6];
#pragma unroll
        for (int k = 0; k < 6; k++) {
            int i = tid + k * 256;
            if (sel) {
                int c = i >> 9, rem = i & 511, y = rem >> 4, x4 = rem & 15;
                v[k] = *reinterpret_cast<const float4*>(
                    img + ((b * 3 + c) * 512 + gy * 64 + half * 32 + y) * 512 + gx * 64 + x4 * 4);
            } else v[k] = zero4();
            sm[i] = v[k];
        }
        // fulls1 row p2, this half's 8 sub-patches (1536 f4), from registers
        {
            float4* d4 = reinterpret_cast<float4*>(out + OFF4) + (size_t)p2 * 3072;
#pragma unroll
            for (int k = 0; k < 6; k++) {
                int i = tid + k * 256;
                int c = i >> 9, rem = i & 511, y = rem >> 4, x4 = rem & 15;
                int ny = half * 2 + (y >> 4), nx = x4 >> 2;
                int j = (ny * 4 + nx) * 192 + c * 64 + (y & 15) * 4 + (x4 & 3);
                d4[j] = v[k];
            }
        }
        __syncthreads();
        // resized2 row p2, this half's 96 f4, from smem
        if (tid < 96) {
            float4 o = zero4();
            int c = tid >> 5, rem = tid & 31, yl = rem >> 2, x4i = rem & 3;
            if (sel) {
                int base2 = c * 512 + (4 * yl + 1) * 16 + 4 * x4i;
                float4 q0 = sm[base2], q1 = sm[base2 + 1];
                float4 q2 = sm[base2 + 2], q3 = sm[base2 + 3];
                float4 u0 = sm[base2 + 16], u1 = sm[base2 + 17];
                float4 u2 = sm[base2 + 18], u3 = sm[base2 + 19];
                o.x = (q0.y + q0.z + u0.y + u0.z) * 0.25f;
                o.y = (q1.y + q1.z + u1.y + u1.z) * 0.25f;
                o.z = (q2.y + q2.z + u2.y + u2.z) * 0.25f;
                o.w = (q3.y + q3.z + u3.y + u3.z) * 0.25f;
            }
            int yg = half * 8 + yl;
            reinterpret_cast<float4*>(out + OFF2)[(size_t)p2 * 192 + c * 64 + yg * 4 + x4i] = o;
        }
    }
}

extern "C" void kernel_launch(void* const* d_in, const int* in_sizes, int n_in,
                              void* d_out, int out_size) {
    const float* img = (const float*)d_in[0];   // images  (32,3,512,512)
    const float* i1  = (const float*)d_in[2];   // imp_s1  (32,16,16)
    const float* i2  = (const float*)d_in[3];   // imp_s2  (32,8,8)
    float* out = (float*)d_out;

    mask_kernel<<<32, 256>>>(i1, i2, out);
    mega_kernel<<<NBLK, 256>>>(img, out);
}

// round 17
// speedup vs baseline: 1.0500x; 1.0500x over previous
#include <cuda_runtime.h>

// ---------------------------------------------------------------------------
// PatchTokenizer: hierarchical mask selection + compacted patch gathers.
//   mask_kernel (32 blocks): barrier-free — every block redundantly counts
//     all batches with COALESCED imp reads (c0 = 1024-16*c2-4*c1), derives
//     global offsets locally; own-batch compaction + output_mask segment.
//   mega_kernel (13824 blocks): proven gather sections.
// FINAL configuration (best measured: 81.92 us, rel_err 5.3e-08).
// ---------------------------------------------------------------------------

#define OFF1 25165824
#define OFF2 31457280
#define OFF3 33030144
#define OFF4 58195968
#define OFF5 83361792
#define OFF6 83394560
#define OFF7 83402752
#define OFF8 83404800
#define OFF9 83404803
#define OFF10 83447843
#define OFF11 83447875
#define OFF12 83447908
#define OFF13 83447909

// scratch (allocation-free rule: __device__ globals; rewritten every launch)
__device__ int g_sel0[32768], g_sel1[8192], g_sel2[2048];
__device__ int g_cnt[3];

__device__ __forceinline__ float4 zero4() { return make_float4(0.f, 0.f, 0.f, 0.f); }

// ---- Mask kernel: 32 blocks x 256 threads, no cross-block sync -----------
__global__ void __launch_bounds__(256)
mask_kernel(const float* __restrict__ imp1, const float* __restrict__ imp2,
            float* __restrict__ out) {
    const int b = blockIdx.x, tid = threadIdx.x;
    __shared__ unsigned char sm2all[2048];  // m2 bits, ALL batches
    __shared__ unsigned char sm1[256];      // m1 bits, own batch
    __shared__ int sC1[32], sC2[32];
    __shared__ unsigned short ssel0[1024], ssel1[256], ssel2[64];
    __shared__ int w0[8], w1[8], w2[8];
    __shared__ int sOff0, sOff1, sOff2, sStart, sTotAll;

    // ---- A: m2 bits for all batches (coalesced) --------------------------
#pragma unroll
    for (int k = 0; k < 8; k++) {
        int i = tid + k * 256;
        sm2all[i] = imp2[i] < 0.3f;
    }
    __syncthreads();

    // ---- B: per-batch c1/c2 counts, all batches, COALESCED ----------------
    // warp w handles batches 4w..4w+3; lane l reads imp1[bb*256 + k*32 + l]
    {
        const int w = tid >> 5, l = tid & 31;
#pragma unroll
        for (int q = 0; q < 4; q++) {
            int bb = w * 4 + q;
            int c2p = (int)sm2all[bb * 64 + l] + (int)sm2all[bb * 64 + 32 + l];
            int c1p = 0;
#pragma unroll
            for (int k = 0; k < 8; k++) {
                int j = k * 32 + l;
                int r = j >> 4, c = j & 15;
                unsigned char cov2 = sm2all[bb * 64 + ((r >> 1) << 3) + (c >> 1)];
                c1p += (imp1[bb * 256 + j] < 0.5f) && !cov2;
            }
#pragma unroll
            for (int o = 16; o; o >>= 1) {
                c2p += __shfl_down_sync(0xffffffffu, c2p, o);
                c1p += __shfl_down_sync(0xffffffffu, c1p, o);
            }
            if (l == 0) { sC1[bb] = c1p; sC2[bb] = c2p; }
        }
    }
    __syncthreads();

    // ---- C: local stitch scan (warp 0; c0 derived analytically) -----------
    if (tid < 32) {
        int c1 = sC1[tid], c2 = sC2[tid];
        int c0 = 1024 - 16 * c2 - 4 * c1;
        int sl = 1 + c0 + c1 + c2;
        int x0 = c0, x1 = c1, x2 = c2, xs = sl;
#pragma unroll
        for (int o = 1; o < 32; o <<= 1) {
            int n0 = __shfl_up_sync(0xffffffffu, x0, o);
            int n1 = __shfl_up_sync(0xffffffffu, x1, o);
            int n2 = __shfl_up_sync(0xffffffffu, x2, o);
            int ns = __shfl_up_sync(0xffffffffu, xs, o);
            if (tid >= o) { x0 += n0; x1 += n1; x2 += n2; xs += ns; }
        }
        if (tid == b) {
            sOff0 = x0 - c0; sOff1 = x1 - c1; sOff2 = x2 - c2;
            sStart = xs - sl;
        }
        if (tid == 31) sTotAll = xs;
        if (b == 0) {
            out[OFF10 + tid] = (float)sl;
            out[OFF11 + 1 + tid] = (float)xs;
            int mx = sl;
#pragma unroll
            for (int o = 16; o; o >>= 1) {
                int n = __shfl_xor_sync(0xffffffffu, mx, o);
                mx = mx > n ? mx : n;
            }
            if (tid == 0) {
                out[OFF11] = 0.0f;
                out[OFF12] = (float)mx;
            }
            if (tid == 31) {
                g_cnt[0] = x0; g_cnt[1] = x1; g_cnt[2] = x2;
                out[OFF8 + 0] = (float)x0;
                out[OFF8 + 1] = (float)x1;
                out[OFF8 + 2] = (float)x2;
                out[OFF13] = (float)xs / 32768.0f;
            }
        }
    }
    __syncthreads();

    // ---- D: own-batch masks + compaction ---------------------------------
    unsigned char v2 = 0;
    if (tid < 64) {
        v2 = sm2all[b * 64 + tid];
        out[OFF7 + b * 64 + tid] = (float)v2;
    }
    unsigned char v1;
    {
        int r = tid >> 4, c = tid & 15;
        unsigned char cov2 = sm2all[b * 64 + ((r >> 1) << 3) + (c >> 1)];
        v1 = (imp1[b * 256 + tid] < 0.5f) && !cov2;
        sm1[tid] = v1;
        out[OFF6 + b * 256 + tid] = (float)v1;
    }
    __syncthreads();

    unsigned char v0[4];
#pragma unroll
    for (int k = 0; k < 4; k++) {
        int j = tid * 4 + k;
        int r = j >> 5, c = j & 31;
        unsigned char cov = sm2all[b * 64 + ((r >> 2) << 3) + (c >> 2)] |
                            sm1[((r >> 1) << 4) + (c >> 1)];
        v0[k] = !cov;
        out[OFF5 + b * 1024 + j] = (float)v0[k];
    }

    const int lane = tid & 31, wid = tid >> 5;
    int s0 = v0[0] + v0[1] + v0[2] + v0[3];
    int a1 = (int)v1, a2 = (tid < 64) ? (int)v2 : 0;
    int i0 = s0, i1 = a1, i2 = a2;
#pragma unroll
    for (int o = 1; o < 32; o <<= 1) {
        int n0 = __shfl_up_sync(0xffffffffu, i0, o);
        int n1 = __shfl_up_sync(0xffffffffu, i1, o);
        int n2 = __shfl_up_sync(0xffffffffu, i2, o);
        if (lane >= o) { i0 += n0; i1 += n1; i2 += n2; }
    }
    if (lane == 31) { w0[wid] = i0; w1[wid] = i1; w2[wid] = i2; }
    __syncthreads();
    int base0 = 0, base1 = 0, base2 = 0, tot0 = 0, tot1 = 0, tot2 = 0;
#pragma unroll
    for (int k = 0; k < 8; k++) {
        if (k < wid) { base0 += w0[k]; base1 += w1[k]; base2 += w2[k]; }
        tot0 += w0[k]; tot1 += w1[k]; tot2 += w2[k];
    }
    {
        int r = base0 + i0 - s0;
#pragma unroll
        for (int k = 0; k < 4; k++)
            if (v0[k]) ssel0[r++] = (unsigned short)(tid * 4 + k);
    }
    if (v1) ssel1[base1 + i1 - a1] = (unsigned short)tid;
    if (tid < 64 && v2) ssel2[base2 + i2 - a2] = (unsigned short)tid;
    __syncthreads();

    // ---- global sel entries for own batch --------------------------------
    for (int r = tid; r < tot0; r += 256)
        g_sel0[sOff0 + r] = (int)ssel0[r] + (b << 10);
    for (int r = tid; r < tot1; r += 256)
        g_sel1[sOff1 + r] = (int)ssel1[r] + (b << 8);
    for (int r = tid; r < tot2; r += 256)
        g_sel2[sOff2 + r] = (int)ssel2[r] + (b << 6);

    // ---- output_mask: own segment (range compare) + tail chunk ------------
    {
        const int seg = 1 + tot0 + tot1 + tot2;
        const int t01 = 1 + tot0;
        const int t012 = 1 + tot0 + tot1;
        for (int i = tid; i < seg; i += 256) {
            float v;
            if (i == 0) v = -1.0f;
            else if (i < t01) v = 1.0f;
            else if (i < t012) v = 2.0f;
            else v = 3.0f;
            out[OFF9 + sStart + i] = v;
        }
        const int tot = sTotAll;
        const int tail = 43040 - tot;
        const int chunk = (tail + 31) >> 5;
        const int lo = tot + b * chunk;
        int hi = lo + chunk;
        if (hi > 43040) hi = 43040;
        for (int j = lo + tid; j < hi; j += 256) out[OFF9 + j] = 0.0f;
    }
}

// ---------------------------------------------------------------------------
// Mega kernel: five big gather sections (proven, unchanged)
// ---------------------------------------------------------------------------
#define NB0 3072
#define NB1 3072
#define NB2 1536
#define NB3 3072
#define NB4 3072
#define E0 (NB0)
#define E1 (NB0 + NB1)
#define E2 (NB0 + NB1 + NB2)
#define E3 (NB0 + NB1 + NB2 + NB3)
#define E4 (NB0 + NB1 + NB2 + NB3 + NB4)   // 13824

__global__ void __launch_bounds__(256)
mega_kernel(const float* __restrict__ img, float* __restrict__ out) {
    const int bs = blockIdx.x;
    const int tid = threadIdx.x;

    if (bs < E0) {
        // ---- S0: resized0 (pure copy of 16x16 base patches) --------------
        const int cnt = g_cnt[0];
        const int base = bs * 2048 + tid;
        int off[8];
#pragma unroll
        for (int k = 0; k < 8; k++) {
            int i = base + k * 256;
            int p = i / 192, t4 = i - p * 192;
            if (p < cnt) {
                int s = g_sel0[p];
                int b = s >> 10, gy = (s >> 5) & 31, gx = s & 31;
                int e = t4 << 2;
                int c = e >> 8, y = (e >> 4) & 15, x = e & 15;
                off[k] = ((b * 3 + c) * 512 + gy * 16 + y) * 512 + gx * 16 + x;
            } else off[k] = -1;
        }
        float4 v[8];
#pragma unroll
        for (int k = 0; k < 8; k++)
            v[k] = (off[k] >= 0) ? *reinterpret_cast<const float4*>(img + off[k]) : zero4();
        float4* dst = reinterpret_cast<float4*>(out);
#pragma unroll
        for (int k = 0; k < 8; k++) dst[base + k * 256] = v[k];

    } else if (bs < E1) {
        // ---- S1: resized1 (2x2 average of original) -----------------------
        const int cnt = g_cnt[1];
        const int base = (bs - E0) * 512 + tid;
        int off[2];
#pragma unroll
        for (int k = 0; k < 2; k++) {
            int i = base + k * 256;
            int p = i / 192, t4 = i - p * 192;
            if (p < cnt) {
                int s = g_sel1[p];
                int b = s >> 8, gy = (s >> 4) & 15, gx = s & 15;
                int e = t4 << 2;
                int c = e >> 8, y = (e >> 4) & 15, x = e & 15;
                int R = gy * 32 + 2 * y, Cc = gx * 32 + 2 * x;
                off[k] = ((b * 3 + c) * 512 + R) * 512 + Cc;
            } else off[k] = -1;
        }
        float4 a0[2], a1[2], b0[2], b1[2];
#pragma unroll
        for (int k = 0; k < 2; k++) {
            if (off[k] >= 0) {
                const float* bp = img + off[k];
                a0[k] = *(const float4*)(bp);
                a1[k] = *(const float4*)(bp + 4);
                b0[k] = *(const float4*)(bp + 512);
                b1[k] = *(const float4*)(bp + 516);
            }
        }
        float4* dst = reinterpret_cast<float4*>(out + OFF1);
#pragma unroll
        for (int k = 0; k < 2; k++) {
            float4 o = zero4();
            if (off[k] >= 0) {
                o.x = (a0[k].x + a0[k].y + b0[k].x + b0[k].y) * 0.25f;
                o.y = (a0[k].z + a0[k].w + b0[k].z + b0[k].w) * 0.25f;
                o.z = (a1[k].x + a1[k].y + b1[k].x + b1[k].y) * 0.25f;
                o.w = (a1[k].z + a1[k].w + b1[k].z + b1[k].w) * 0.25f;
            }
            dst[base + k * 256] = o;
        }

    } else if (bs < E2) {
        // ---- S2: resized2 (central 2x2 average, 4x downsample) ------------
        const int cnt = g_cnt[2];
        const int i = (bs - E1) * 256 + tid;
        const int p = i / 192, t4 = i - p * 192;
        float4 o = zero4();
        if (p < cnt) {
            int s = g_sel2[p];
            int b = s >> 6, gy = (s >> 3) & 7, gx = s & 7;
            int e = t4 << 2;
            int c = e >> 8, y = (e >> 4) & 15, x = e & 15;
            int R0 = gy * 64 + 4 * y + 1;
            int Cb = gx * 64 + 4 * x;
            const float* r0 = img + ((b * 3 + c) * 512 + R0) * 512 + Cb;
            const float* r1 = r0 + 512;
            float4 q0 = *(const float4*)r0, q1 = *(const float4*)(r0 + 4);
            float4 q2 = *(const float4*)(r0 + 8), q3 = *(const float4*)(r0 + 12);
            float4 u0 = *(const float4*)r1, u1 = *(const float4*)(r1 + 4);
            float4 u2 = *(const float4*)(r1 + 8), u3 = *(const float4*)(r1 + 12);
            o.x = (q0.y + q0.z + u0.y + u0.z) * 0.25f;
            o.y = (q1.y + q1.z + u1.y + u1.z) * 0.25f;
            o.z = (q2.y + q2.z + u2.y + u2.z) * 0.25f;
            o.w = (q3.y + q3.z + u3.y + u3.z) * 0.25f;
        }
        reinterpret_cast<float4*>(out + OFF2)[i] = o;

    } else if (bs < E3) {
        // ---- S3: fulls0 (2x2 constituent base patches, pure copy) ---------
        const int cnt = g_cnt[1];
        const int base = (bs - E2) * 2048 + tid;
        int off[8];
#pragma unroll
        for (int k = 0; k < 8; k++) {
            int i = base + k * 256;
            int p = i / 768, rf = i - p * 768;
            if (p < cnt) {
                int s = g_sel1[p];
                int b = s >> 8, gy = (s >> 4) & 15, gx = s & 15;
                int e = rf << 2;
                int sub = e / 768, rem = e - sub * 768;
                int c = rem >> 8, y = (rem >> 4) & 15, x = rem & 15;
                int ny = sub >> 1, nx = sub & 1;
                int R = gy * 32 + ny * 16 + y, Cc = gx * 32 + nx * 16 + x;
                off[k] = ((b * 3 + c) * 512 + R) * 512 + Cc;
            } else off[k] = -1;
        }
        float4 v[8];
#pragma unroll
        for (int k = 0; k < 8; k++)
            v[k] = (off[k] >= 0) ? *reinterpret_cast<const float4*>(img + off[k]) : zero4();
        float4* dst = reinterpret_cast<float4*>(out + OFF3);
#pragma unroll
        for (int k = 0; k < 8; k++) dst[base + k * 256] = v[k];

    } else {
        // ---- S4: fulls1 (4x4 constituent base patches, pure copy) ---------
        const int cnt = g_cnt[2];
        const int base = (bs - E3) * 2048 + tid;
        int off[8];
#pragma unroll
        for (int k = 0; k < 8; k++) {
            int i = base + k * 256;
            int p = i / 3072, rf = i - p * 3072;
            if (p < cnt) {
                int s = g_sel2[p];
                int b = s >> 6, gy = (s >> 3) & 7, gx = s & 7;
                int e = rf << 2;
                int sub = e / 768, rem = e - sub * 768;
                int c = rem >> 8, y = (rem >> 4) & 15, x = rem & 15;
                int ny = sub >> 2, nx = sub & 3;
                int R = gy * 64 + ny * 16 + y, Cc = gx * 64 + nx * 16 + x;
                off[k] = ((b * 3 + c) * 512 + R) * 512 + Cc;
            } else off[k] = -1;
        }
        float4 v[8];
#pragma unroll
        for (int k = 0; k < 8; k++)
            v[k] = (off[k] >= 0) ? *reinterpret_cast<const float4*>(img + off[k]) : zero4();
        float4* dst = reinterpret_cast<float4*>(out + OFF4);
#pragma unroll
        for (int k = 0; k < 8; k++) dst[base + k * 256] = v[k];
    }
}

extern "C" void kernel_launch(void* const* d_in, const int* in_sizes, int n_in,
                              void* d_out, int out_size) {
    const float* img = (const float*)d_in[0];   // images  (32,3,512,512)
    const float* i1  = (const float*)d_in[2];   // imp_s1  (32,16,16)
    const float* i2  = (const float*)d_in[3];   // imp_s2  (32,8,8)
    float* out = (float*)d_out;

    mask_kernel<<<32, 256>>>(i1, i2, out);
    mega_kernel<<<E4, 256>>>(img, out);
}